// round 16
// baseline (speedup 1.0000x reference)
#include <cuda_runtime.h>
#include <math.h>

#define BB 8
#define MM 3072
#define CC 10
#define HH 128
#define KK 32
#define GG 24                 // grid cells per axis; 1/24 > 0.04 radius
#define NCELL (GG * GG)       // 576
#define CAP 48                // per-particle candidate-hit capacity (lambda~15)
#define NPW 8                 // warps per block
#define FROW 28               // feature row stride in floats (112B, conflict-free STS.128)
#define NBLK 296              // 2 blocks per SM on 148 SMs, single wave
#define TOTP (BB * MM)        // 24576 particles (even -> chunk of 2 never splits)
#define RADIUSF 0.04f
#define ACC_SCALEF 0.02f
#define MAX_VELF 0.02f
#define NOISEF 0.002f

typedef unsigned long long ull;

// Scratch (no cudaMalloc allowed)
__device__ float4 g_sorted[BB * MM];            // {x, y, id_as_float_bits, pad}
__device__ int    g_cell_off[BB * (NCELL + 1)]; // exclusive offsets per batch
__device__ int    g_ctr;                        // dynamic work counter

__device__ __forceinline__ int cell_of(float p) {
    int c = (int)(p * (float)GG);
    return c > GG - 1 ? GG - 1 : c;
}

// ---- f32x2 packed helpers (sm_100+) ---------------------------------------
__device__ __forceinline__ ull pack2(float lo, float hi) {
    ull d; asm("mov.b64 %0, {%1, %2};" : "=l"(d) : "f"(lo), "f"(hi)); return d;
}
__device__ __forceinline__ void unpack2(ull v, float &lo, float &hi) {
    asm("mov.b64 {%0, %1}, %2;" : "=f"(lo), "=f"(hi) : "l"(v));
}
__device__ __forceinline__ ull fma2(ull a, ull b, ull c) {
    ull d; asm("fma.rn.f32x2 %0, %1, %2, %3;" : "=l"(d) : "l"(a), "l"(b), "l"(c));
    return d;
}
__device__ __forceinline__ ull add2(ull a, ull b) {
    ull d; asm("add.rn.f32x2 %0, %1, %2;" : "=l"(d) : "l"(a), "l"(b));
    return d;
}
__device__ __forceinline__ void lds2x64(ull &a, ull &b, unsigned addr) {
    asm volatile("ld.shared.v2.b64 {%0, %1}, [%2];" : "=l"(a), "=l"(b) : "r"(addr));
}
__device__ __forceinline__ void lds64(ull &a, unsigned addr) {
    asm volatile("ld.shared.b64 %0, [%1];" : "=l"(a) : "r"(addr));
}
__device__ __forceinline__ unsigned smem_u32(const void* p) {
    return (unsigned)__cvta_generic_to_shared(p);
}

// ---------------------------------------------------------------------------
// Kernel 0: build cell-sorted particle list. One block per batch.
// Also resets the dynamic-work counter (stream-ordered before fused_kernel).
// ---------------------------------------------------------------------------
#define TPB_G 1024
__global__ void __launch_bounds__(TPB_G) build_grid_kernel(const float* __restrict__ x)
{
    __shared__ int s_cnt[NCELL];
    __shared__ int s_wsum[TPB_G / 32];
    __shared__ int s_cur[NCELL];

    const int b = blockIdx.x;
    const int tid = threadIdx.x;
    const int wid = tid >> 5, lane = tid & 31;
    const unsigned FULL = 0xffffffffu;
    const float* xb = x + (size_t)b * MM * CC;

    if (b == 0 && tid == 0) g_ctr = 0;
    if (tid < NCELL) s_cnt[tid] = 0;
    __syncthreads();

    int   myc[MM / TPB_G];
    float mpx[MM / TPB_G], mpy[MM / TPB_G];
    #pragma unroll
    for (int r = 0; r < MM / TPB_G; r++) {
        const int i = tid + r * TPB_G;
        const float2 pv = __ldg((const float2*)(xb + (size_t)i * CC)); // LDG.64
        const int c = cell_of(pv.y) * GG + cell_of(pv.x);
        myc[r] = c; mpx[r] = pv.x; mpy[r] = pv.y;
        atomicAdd(&s_cnt[c], 1);
    }
    __syncthreads();

    int val = (tid < NCELL) ? s_cnt[tid] : 0;
    int incl = val;
    #pragma unroll
    for (int o = 1; o < 32; o <<= 1) {
        int v = __shfl_up_sync(FULL, incl, o);
        if (lane >= o) incl += v;
    }
    if (lane == 31) s_wsum[wid] = incl;
    __syncthreads();
    if (wid == 0) {
        int wv = (lane < TPB_G / 32) ? s_wsum[lane] : 0;
        int wi = wv;
        #pragma unroll
        for (int o = 1; o < 32; o <<= 1) {
            int v = __shfl_up_sync(FULL, wi, o);
            if (lane >= o) wi += v;
        }
        if (lane < TPB_G / 32) s_wsum[lane] = wi - wv;
    }
    __syncthreads();
    if (tid < NCELL) {
        const int excl = s_wsum[wid] + incl - val;
        s_cur[tid] = excl;
        g_cell_off[b * (NCELL + 1) + tid] = excl;
    }
    if (tid == 0) g_cell_off[b * (NCELL + 1) + NCELL] = MM;
    __syncthreads();

    #pragma unroll
    for (int r = 0; r < MM / TPB_G; r++) {
        const int i = tid + r * TPB_G;
        const int slot = atomicAdd(&s_cur[myc[r]], 1);
        __stcs(&g_sorted[(size_t)b * MM + slot],
               make_float4(mpx[r], mpy[r], __int_as_float(i), 0.0f));
    }
}

// ---------------------------------------------------------------------------
// Persistent fused kernel: dynamic chunks of 2 particles; MLP loop unrolled
// by 2 edges (4 independent fma2 chains/warp); W2/b2 loaded per particle.
// ---------------------------------------------------------------------------
__global__ void __launch_bounds__(256, 2) fused_kernel(
    const float* __restrict__ x,  const float* __restrict__ W1,
    const float* __restrict__ b1, const float* __restrict__ W2,
    const float* __restrict__ b2, const float* __restrict__ noise_u,
    float* __restrict__ out)
{
    __shared__ float s_cdx[NPW][CAP], s_cdy[NPW][CAP], s_cds[NPW][CAP];
    __shared__ int   s_cj [NPW][CAP];
    __shared__ __align__(16) float s_feat[NPW][KK * FROW];
    __shared__ int   s_astart[NPW][9];
    __shared__ int   s_bound [NPW][10];

    const unsigned FULL = 0xffffffffu;
    const int warp = threadIdx.x >> 5;
    const int lane = threadIdx.x & 31;
    const int p = warp;

    // ---- W1/b1 prologue: ONCE per warp -------------------------------------
    ull wA[11], wB[11];
    {
        const float4 wf11 = __ldg(&((const float4*)(W1 + 11 * HH))[lane]);
        #pragma unroll
        for (int f = 0; f < 11; f++) {
            float4 wf = __ldg(&((const float4*)(W1 + f * HH))[lane]);
            if (f == 2) {   // fold duplicated feature: msg[11] == msg[2]
                wf.x += wf11.x; wf.y += wf11.y;
                wf.z += wf11.z; wf.w += wf11.w;
            }
            wA[f] = pack2(wf.x, wf.y);
            wB[f] = pack2(wf.z, wf.w);
        }
    }
    const float4 bv = __ldg(&((const float4*)b1)[lane]);
    const ull bA = pack2(bv.x, bv.y);
    const ull bB = pack2(bv.z, bv.w);
    const int h0 = 4 * lane;
    const ull HALF2 = pack2(0.5f, 0.5f);
    const ull ABSM  = 0x7fffffff7fffffffULL;

    // one edge's 11-fma2 dual chain (independent per call site)
    auto edge_chains = [&](unsigned raddr, ull &tA, ull &tB) {
        ull q0, q1, q2, q3;
        tA = bA; tB = bB;
        lds2x64(q0, q1, raddr);          // f0, f1
        lds2x64(q2, q3, raddr + 16);     // f2, f3
        tA = fma2(q0, wA[0], tA);  tB = fma2(q0, wB[0], tB);
        tA = fma2(q1, wA[1], tA);  tB = fma2(q1, wB[1], tB);
        lds2x64(q0, q1, raddr + 32);     // f4, f5
        tA = fma2(q2, wA[2], tA);  tB = fma2(q2, wB[2], tB);
        tA = fma2(q3, wA[3], tA);  tB = fma2(q3, wB[3], tB);
        lds2x64(q2, q3, raddr + 48);     // f6, f7
        tA = fma2(q0, wA[4], tA);  tB = fma2(q0, wB[4], tB);
        tA = fma2(q1, wA[5], tA);  tB = fma2(q1, wB[5], tB);
        lds2x64(q0, q1, raddr + 64);     // f8, f9
        tA = fma2(q2, wA[6], tA);  tB = fma2(q2, wB[6], tB);
        tA = fma2(q3, wA[7], tA);  tB = fma2(q3, wB[7], tB);
        lds64(q2, raddr + 80);           // f10
        tA = fma2(q0, wA[8], tA);  tB = fma2(q0, wB[8], tB);
        tA = fma2(q1, wA[9], tA);  tB = fma2(q1, wB[9], tB);
        tA = fma2(q2, wA[10], tA); tB = fma2(q2, wB[10], tB);
    };

    // ---- per-particle processing --------------------------------------------
    auto process = [&](int sidx, const float4 me) {
        const int b = sidx / MM;
        const int myslot = sidx - b * MM;
        const float pix = me.x, piy = me.y;
        const int   grow = b * MM + __float_as_int(me.z);

        // early prefetch: own row + noise (used ~2000 cycles later)
        const float xv = (lane < CC) ? __ldg(&x[(size_t)grow * CC + lane]) : 0.0f;
        const float nz = (lane < 3)  ? __ldg(&noise_u[(size_t)grow * 3 + lane]) : 0.0f;
        const bool is_cell = (__shfl_sync(FULL, xv, 4) == 1.0f);

        // ---------------- search ----------------
        const int cix = cell_of(pix);
        const int ciy = cell_of(piy);
        int len = 0, t0 = 0;
        if (lane < 9) {
            int cy = ciy + (lane / 3) - 1; if (cy < 0) cy += GG; if (cy >= GG) cy -= GG;
            int cx = cix + (lane % 3) - 1; if (cx < 0) cx += GG; if (cx >= GG) cx -= GG;
            const int c = cy * GG + cx;
            t0  = g_cell_off[b * (NCELL + 1) + c];
            len = g_cell_off[b * (NCELL + 1) + c + 1] - t0;
        }
        int incl = len;
        #pragma unroll
        for (int o = 1; o < 16; o <<= 1) {
            int v = __shfl_up_sync(FULL, incl, o);
            if (lane >= o) incl += v;
        }
        const int T = __shfl_sync(FULL, incl, 8);
        if (lane < 9) {
            const int excl = incl - len;
            s_astart[p][lane] = t0 - excl;
            s_bound [p][lane] = excl;
        }
        __syncwarp();

        const float4* __restrict__ sb = g_sorted + (size_t)b * MM;
        auto slot_of = [&](int kk) -> int {
            int q = 0;
            #pragma unroll
            for (int t = 1; t < 9; t++)
                if (kk >= s_bound[p][t]) q = t;
            return s_astart[p][q] + kk;
        };

        const int k0 = lane, k1 = lane + 32;
        int ts0 = 0, ts1 = 0;
        float4 cand0 = make_float4(0.f, 0.f, 0.f, 0.f);
        float4 cand1 = make_float4(0.f, 0.f, 0.f, 0.f);
        if (k0 < T) { ts0 = slot_of(k0); cand0 = __ldg(&sb[ts0]); }
        if (k1 < T) { ts1 = slot_of(k1); cand1 = __ldg(&sb[ts1]); }

        int hits = 0;
        #pragma unroll
        for (int rnd = 0; rnd < 2; rnd++) {
            const int     kc   = rnd ? k1 : k0;
            const int     tslt = rnd ? ts1 : ts0;
            const float4  cand = rnd ? cand1 : cand0;
            bool pred = false;
            float dx = 0.f, dy = 0.f, dist = 0.f;
            if (kc < T) {
                dx = pix - cand.x; dx -= rintf(dx);
                dy = piy - cand.y; dy -= rintf(dy);
                dist = sqrtf(dx * dx + dy * dy + 1e-12f);
                pred = (dist < RADIUSF) && (tslt != myslot);
            }
            const unsigned m = __ballot_sync(FULL, pred);
            if (pred) {
                const int pos = hits + __popc(m & ((1u << lane) - 1));
                if (pos < CAP) {
                    s_cj [p][pos] = __float_as_int(cand.z);
                    s_cdx[p][pos] = dx;
                    s_cdy[p][pos] = dy;
                    s_cds[p][pos] = dist;
                }
            }
            hits += __popc(m);
        }
        // rare: T > 64
        for (int base2 = 64; base2 < T; base2 += 32) {
            const int kc = base2 + lane;
            bool pred = false;
            int  cid = 0;
            float dx = 0.f, dy = 0.f, dist = 0.f;
            if (kc < T) {
                const int tslot = slot_of(kc);
                const float4 cand = __ldg(&sb[tslot]);
                dx = pix - cand.x; dx -= rintf(dx);
                dy = piy - cand.y; dy -= rintf(dy);
                dist = sqrtf(dx * dx + dy * dy + 1e-12f);
                pred = (dist < RADIUSF) && (tslot != myslot);
                cid = __float_as_int(cand.z);
            }
            const unsigned m = __ballot_sync(FULL, pred);
            if (pred) {
                const int pos = hits + __popc(m & ((1u << lane) - 1));
                if (pos < CAP) {
                    s_cj [p][pos] = cid;
                    s_cdx[p][pos] = dx;
                    s_cdy[p][pos] = dy;
                    s_cds[p][pos] = dist;
                }
            }
            hits += __popc(m);
        }
        if (hits > CAP) hits = CAP;
        __syncwarp();

        // rare: rank-select KK nearest (edge order dead: edges are summed)
        if (hits > KK) {
            float* stage = &s_feat[p][0];
            int*   stagei = (int*)&s_feat[p][3 * KK];
            for (int h = lane; h < hits; h += 32) {
                const float dh = s_cds[p][h];
                int rank = 0;
                for (int g2 = 0; g2 < hits; g2++) {
                    const float dg = s_cds[p][g2];
                    rank += (dg < dh) || (dg == dh && g2 < h);
                }
                if (rank < KK) {
                    stage[rank]          = s_cdx[p][h];
                    stage[KK + rank]     = s_cdy[p][h];
                    stage[2 * KK + rank] = dh;
                    stagei[rank]         = s_cj[p][h];
                }
            }
            __syncwarp();
            if (lane < KK) {
                s_cdx[p][lane] = stage[lane];
                s_cdy[p][lane] = stage[KK + lane];
                s_cds[p][lane] = stage[2 * KK + lane];
                s_cj [p][lane] = stagei[lane];
            }
            hits = KK;
            __syncwarp();
        }
        const int cnt = hits;

        // ---------------- gather features (lane = edge) ----------------
        float c4v = 0.0f;
        if (lane < cnt) {
            const float2* xp = (const float2*)(x + ((size_t)b * MM + s_cj[p][lane]) * CC);
            const float2 a2 = __ldg(&xp[2]);    // cell, rest0
            c4v = a2.x;
            if (is_cell) {
                const float2 a1 = __ldg(&xp[1]);
                const float2 a3 = __ldg(&xp[3]);
                const float2 a4 = __ldg(&xp[4]);
                float4* row = (float4*)&s_feat[p][lane * FROW];
                const float ds = s_cds[p][lane];
                const float dx = s_cdx[p][lane];
                const float dy = s_cdy[p][lane];
                row[0] = make_float4(a1.x, a1.x, a1.y, a1.y);
                row[1] = make_float4(a2.x, a2.x, a2.y, a2.y);
                row[2] = make_float4(a3.x, a3.x, a3.y, a3.y);
                row[3] = make_float4(a4.x, a4.x, a4.y, a4.y);
                row[4] = make_float4(ds,   ds,   dx,   dx);
                row[5] = make_float4(dy,   dy,   0.f,  0.f);
            }
        }
        const int deg_cell = __popc(__ballot_sync(FULL, (lane < cnt) && (c4v == 1.0f)));
        __syncwarp();

        // ---------------- edge MLP (packed f32x2, 2-edge unrolled) -----------
        float o0 = 0.0f, o1 = 0.0f;
        if (is_cell) {
            float agg0 = 0.f, agg1 = 0.f, agg2 = 0.f, agg3 = 0.f;
            if (cnt > 0) {
                ull aggA = pack2(0.f, 0.f), aggB = pack2(0.f, 0.f);
                unsigned raddr = smem_u32(&s_feat[p][0]);
                int e = 0;
                for (; e + 2 <= cnt; e += 2, raddr += 2 * FROW * 4) {
                    ull tAa, tBa, tAb, tBb;
                    edge_chains(raddr, tAa, tBa);                // edge e
                    edge_chains(raddr + FROW * 4, tAb, tBb);     // edge e+1
                    // exact packed relu-accumulate: relu(x) = (x + |x|) * 0.5
                    const ull sAa = add2(tAa, tAa & ABSM);
                    const ull sBa = add2(tBa, tBa & ABSM);
                    const ull sAb = add2(tAb, tAb & ABSM);
                    const ull sBb = add2(tBb, tBb & ABSM);
                    aggA = fma2(sAa, HALF2, aggA);
                    aggB = fma2(sBa, HALF2, aggB);
                    aggA = fma2(sAb, HALF2, aggA);
                    aggB = fma2(sBb, HALF2, aggB);
                }
                if (e < cnt) {                                   // odd trailing edge
                    ull tA, tB;
                    edge_chains(raddr, tA, tB);
                    const ull sA = add2(tA, tA & ABSM);
                    const ull sB = add2(tB, tB & ABSM);
                    aggA = fma2(sA, HALF2, aggA);
                    aggB = fma2(sB, HALF2, aggB);
                }
                unpack2(aggA, agg0, agg1);
                unpack2(aggB, agg2, agg3);
            }

            // agg @ W2[:, 0:2] — W2/b2 per-particle loads (L1-hot), freeing
            // persistent registers to fund the 2-edge unroll.
            float pa0, pa1;
            pa0 = agg0 * __ldg(&W2[(h0 + 0) * 7 + 0]);
            pa0 = fmaf(agg1, __ldg(&W2[(h0 + 1) * 7 + 0]), pa0);
            pa0 = fmaf(agg2, __ldg(&W2[(h0 + 2) * 7 + 0]), pa0);
            pa0 = fmaf(agg3, __ldg(&W2[(h0 + 3) * 7 + 0]), pa0);
            pa1 = agg0 * __ldg(&W2[(h0 + 0) * 7 + 1]);
            pa1 = fmaf(agg1, __ldg(&W2[(h0 + 1) * 7 + 1]), pa1);
            pa1 = fmaf(agg2, __ldg(&W2[(h0 + 2) * 7 + 1]), pa1);
            pa1 = fmaf(agg3, __ldg(&W2[(h0 + 3) * 7 + 1]), pa1);
            #pragma unroll
            for (int sh = 16; sh > 0; sh >>= 1) {
                pa0 += __shfl_xor_sync(FULL, pa0, sh);
                pa1 += __shfl_xor_sync(FULL, pa1, sh);
            }
            o0 = pa0 + __ldg(&b2[0]);
            o1 = pa1 + __ldg(&b2[1]);
        }

        // ---------------- epilogue (all lanes redundantly) ----------------
        {
            const float vx = __shfl_sync(FULL, xv, 2);
            const float vy = __shfl_sync(FULL, xv, 3);
            float nvx = vx, nvy = vy, npx = pix, npy = piy;

            if (is_cell) {
                float ax = tanhf(o0) * ACC_SCALEF;
                float ay = tanhf(o1) * ACC_SCALEF;
                float ux = vx + ax, uy = vy + ay;
                float sp = sqrtf(ux * ux + uy * uy);
                float sc = fminf(1.0f, MAX_VELF / (sp + 1e-12f));
                ux *= sc; uy *= sc;
                npx = pix + ux; npx -= floorf(npx);
                npy = piy + uy; npy -= floorf(npy);
                const float u0 = __shfl_sync(FULL, nz, 0);
                const float u1 = __shfl_sync(FULL, nz, 1);
                const float u2 = __shfl_sync(FULL, nz, 2);
                const float nm = (u2 > 0.5f) ? 1.0f : 0.0f;
                nvx = ux + (u0 * 2.0f - 1.0f) * NOISEF * nm;
                nvy = uy + (u1 * 2.0f - 1.0f) * NOISEF * nm;
            }

            const bool dead     =  is_cell && (deg_cell < 1);
            const bool consumed = !is_cell && (deg_cell >= 1);
            const float keep = (dead || consumed) ? 0.0f : 1.0f;

            if (lane < CC) {
                float val = xv;                   // lanes 4..9: passthrough
                if (lane == 0) val = npx;
                else if (lane == 1) val = npy;
                else if (lane == 2) val = nvx;
                else if (lane == 3) val = nvy;
                out[(size_t)grow * CC + lane] = val * keep;
            }
        }
    };

    // ---- dynamic work loop: chunks of 2, grabbed one chunk ahead ------------
    auto warp_grab = [&]() -> int {
        int v = 0;
        if (lane == 0) v = atomicAdd(&g_ctr, 2);
        return __shfl_sync(FULL, v, 0);
    };

    int base = warp_grab();
    float4 me0 = (base < TOTP) ? g_sorted[base]
                               : make_float4(0.f, 0.f, 0.f, 0.f);
    int nbase = warp_grab();
    float4 me_n = (nbase < TOTP) ? g_sorted[nbase]
                                 : make_float4(0.f, 0.f, 0.f, 0.f);

    while (base < TOTP) {                        // warp-uniform
        // base is even and TOTP even -> base+1 always valid
        const float4 me1 = g_sorted[base + 1];   // hidden behind process(base)
        process(base, me0);
        process(base + 1, me1);
        base = nbase; me0 = me_n;
        nbase = warp_grab();
        me_n = (nbase < TOTP) ? g_sorted[nbase]
                              : make_float4(0.f, 0.f, 0.f, 0.f);
    }
}

// ---------------------------------------------------------------------------
extern "C" void kernel_launch(void* const* d_in, const int* in_sizes, int n_in,
                              void* d_out, int out_size)
{
    const float* x       = (const float*)d_in[0];
    const float* W1      = (const float*)d_in[1];
    const float* b1      = (const float*)d_in[2];
    const float* W2      = (const float*)d_in[3];
    const float* b2      = (const float*)d_in[4];
    const float* noise_u = (const float*)d_in[5];
    float* out = (float*)d_out;

    build_grid_kernel<<<BB, TPB_G>>>(x);
    fused_kernel<<<NBLK, NPW * 32>>>(x, W1, b1, W2, b2, noise_u, out);
}